// round 1
// baseline (speedup 1.0000x reference)
#include <cuda_runtime.h>

#define N_VOX 1000000
#define KVOL  27
#define C_IN  3
#define C_HID 64
#define C_OUT 3
#define BN_EPS 1e-5f

// Scratch (device globals: allocation-free per harness rules)
__device__ float  g_h[(size_t)N_VOX * C_HID];     // 256 MB: conv1 output
__device__ float4 g_z[(size_t)KVOL * N_VOX];      // 432 MB: per-offset partial outputs
__device__ float  g_stats[4 * C_HID];             // sum, sumsq, scale, shift

typedef unsigned long long u64;

__device__ __forceinline__ u64 pack2(float lo, float hi) {
    u64 r; asm("mov.b64 %0, {%1, %2};" : "=l"(r) : "f"(lo), "f"(hi)); return r;
}
__device__ __forceinline__ void unpack2(u64 v, float& lo, float& hi) {
    asm("mov.b64 {%0, %1}, %2;" : "=f"(lo), "=f"(hi) : "l"(v));
}
#define FMA2(d, a, b, c) asm("fma.rn.f32x2 %0, %1, %2, %3;" : "=l"(d) : "l"(a), "l"(b), "l"(c))

// ---------------------------------------------------------------------------
__global__ void zero_stats_kernel() {
    int i = threadIdx.x;
    if (i < 2 * C_HID) g_stats[i] = 0.f;
}

// ---------------------------------------------------------------------------
// conv1: h[n,:] = sum_k feats[nbr[k,n]] @ W1[k]   (masked)
__global__ __launch_bounds__(256) void conv1_kernel(const float* __restrict__ feats,
                                                    const float* __restrict__ W1,
                                                    const int*   __restrict__ nbr) {
    __shared__ u64 w1s[KVOL * C_IN * C_HID / 2];   // 2592 u64 = 20736 B, layout [k][c][d-pair]
    {
        const u64* w1g = (const u64*)W1;
        for (int i = threadIdx.x; i < KVOL * C_IN * C_HID / 2; i += 256) w1s[i] = w1g[i];
    }
    __syncthreads();
    int n = blockIdx.x * 256 + threadIdx.x;
    if (n >= N_VOX) return;

    u64 acc[C_HID / 2];
    #pragma unroll
    for (int p = 0; p < C_HID / 2; p++) acc[p] = 0ull;

    #pragma unroll 1
    for (int k = 0; k < KVOL; k++) {
        int idx = nbr[k * N_VOX + n];
        if (idx >= 0) {
            const float* f = feats + 3 * idx;
            float f0 = f[0], f1 = f[1], f2 = f[2];
            u64 a0 = pack2(f0, f0);
            u64 a1 = pack2(f1, f1);
            u64 a2 = pack2(f2, f2);
            const u64* w = w1s + k * 96;           // 96 pairs = 3 c * 32 pairs
            #pragma unroll
            for (int p = 0; p < 32; p++) {
                FMA2(acc[p], a0, w[p],      acc[p]);
                FMA2(acc[p], a1, w[32 + p], acc[p]);
                FMA2(acc[p], a2, w[64 + p], acc[p]);
            }
        }
    }
    float4* ho = (float4*)(g_h + (size_t)n * C_HID);
    #pragma unroll
    for (int j = 0; j < 16; j++) {
        float x, y, z, w;
        unpack2(acc[2 * j],     x, y);
        unpack2(acc[2 * j + 1], z, w);
        ho[j] = make_float4(x, y, z, w);
    }
}

// ---------------------------------------------------------------------------
// BN stats: per-channel sum / sumsq over all N rows of g_h
__global__ __launch_bounds__(256) void stats_kernel() {
    int d = threadIdx.x & 63;
    int r = threadIdx.x >> 6;                       // 0..3
    float s = 0.f, s2 = 0.f;
    for (size_t n = (size_t)blockIdx.x * 4 + r; n < N_VOX; n += (size_t)gridDim.x * 4) {
        float v = g_h[n * C_HID + d];
        s += v; s2 += v * v;
    }
    __shared__ float sm[8][C_HID];
    sm[r][d] = s; sm[4 + r][d] = s2;
    __syncthreads();
    if (r == 0) {
        s  = sm[0][d] + sm[1][d] + sm[2][d] + sm[3][d];
        s2 = sm[4][d] + sm[5][d] + sm[6][d] + sm[7][d];
        atomicAdd(&g_stats[d], s);
        atomicAdd(&g_stats[C_HID + d], s2);
    }
}

__global__ void finalize_kernel(const float* __restrict__ gamma,
                                const float* __restrict__ beta) {
    int d = threadIdx.x;
    if (d < C_HID) {
        float mu  = g_stats[d] * (1.f / N_VOX);
        float var = g_stats[C_HID + d] * (1.f / N_VOX) - mu * mu;
        float sc  = gamma[d] * rsqrtf(var + BN_EPS);
        g_stats[2 * C_HID + d] = sc;
        g_stats[3 * C_HID + d] = beta[d] - mu * sc;
    }
}

// ---------------------------------------------------------------------------
// conv2a: z[k, m] = relu(bn(h[m])) @ W2[26-k]   (dense over all m, k)
__global__ __launch_bounds__(256) void conv2a_kernel(const float* __restrict__ W2) {
    __shared__ u64 w2t[KVOL * C_OUT * C_HID / 2];  // [k'][c][d-pair], k' uses W2[26-k']
    __shared__ float scs[C_HID], shs[C_HID];
    {
        float* w2tf = (float*)w2t;
        for (int i = threadIdx.x; i < KVOL * C_OUT * C_HID; i += 256) {
            int kk  = i / (C_OUT * C_HID);
            int rem = i % (C_OUT * C_HID);
            int c   = rem / C_HID;
            int d   = rem % C_HID;
            w2tf[(kk * C_OUT + c) * C_HID + d] =
                W2[(KVOL - 1 - kk) * (C_HID * C_OUT) + d * C_OUT + c];
        }
        if (threadIdx.x < C_HID) {
            scs[threadIdx.x] = g_stats[2 * C_HID + threadIdx.x];
            shs[threadIdx.x] = g_stats[3 * C_HID + threadIdx.x];
        }
    }
    __syncthreads();
    int m = blockIdx.x * 256 + threadIdx.x;
    if (m >= N_VOX) return;

    // load h row, apply BN + ReLU, keep as f32x2 pairs
    u64 hb[C_HID / 2];
    const float4* hp = (const float4*)(g_h + (size_t)m * C_HID);
    #pragma unroll
    for (int j = 0; j < 16; j++) {
        float4 v = hp[j];
        int d = 4 * j;
        v.x = fmaxf(fmaf(v.x, scs[d + 0], shs[d + 0]), 0.f);
        v.y = fmaxf(fmaf(v.y, scs[d + 1], shs[d + 1]), 0.f);
        v.z = fmaxf(fmaf(v.z, scs[d + 2], shs[d + 2]), 0.f);
        v.w = fmaxf(fmaf(v.w, scs[d + 3], shs[d + 3]), 0.f);
        hb[2 * j]     = pack2(v.x, v.y);
        hb[2 * j + 1] = pack2(v.z, v.w);
    }

    #pragma unroll 1
    for (int k = 0; k < KVOL; k++) {
        u64 acc0 = 0ull, acc1 = 0ull, acc2 = 0ull;
        const u64* w = w2t + k * 96;
        #pragma unroll
        for (int p = 0; p < 32; p++) {
            FMA2(acc0, hb[p], w[p],      acc0);
            FMA2(acc1, hb[p], w[32 + p], acc1);
            FMA2(acc2, hb[p], w[64 + p], acc2);
        }
        float x0, x1, y0, y1, z0, z1;
        unpack2(acc0, x0, x1);
        unpack2(acc1, y0, y1);
        unpack2(acc2, z0, z1);
        g_z[(size_t)k * N_VOX + m] = make_float4(x0 + x1, y0 + y1, z0 + z1, 0.f);
    }
}

// ---------------------------------------------------------------------------
// conv2b: out[n] = sum_k valid(k,n) * z[k, nbr[k,n]]
__global__ __launch_bounds__(256) void conv2b_kernel(const int* __restrict__ nbr,
                                                     float* __restrict__ out) {
    int n = blockIdx.x * 256 + threadIdx.x;
    if (n >= N_VOX) return;
    float a0 = 0.f, a1 = 0.f, a2 = 0.f;
    #pragma unroll
    for (int k = 0; k < KVOL; k++) {
        int idx = nbr[k * N_VOX + n];
        if (idx >= 0) {
            float4 v = __ldg(&g_z[(size_t)k * N_VOX + idx]);
            a0 += v.x; a1 += v.y; a2 += v.z;
        }
    }
    out[3 * n + 0] = a0;
    out[3 * n + 1] = a1;
    out[3 * n + 2] = a2;
}

// ---------------------------------------------------------------------------
extern "C" void kernel_launch(void* const* d_in, const int* in_sizes, int n_in,
                              void* d_out, int out_size) {
    const float* feats = (const float*)d_in[0];
    const float* W1    = (const float*)d_in[1];
    const float* gamma = (const float*)d_in[2];
    const float* beta  = (const float*)d_in[3];
    const float* W2    = (const float*)d_in[4];
    const int*   nbr   = (const int*)  d_in[5];
    float*       out   = (float*)d_out;

    int nblk = (N_VOX + 255) / 256;

    zero_stats_kernel<<<1, 128>>>();
    conv1_kernel<<<nblk, 256>>>(feats, W1, nbr);
    stats_kernel<<<2048, 256>>>();
    finalize_kernel<<<1, 64>>>(gamma, beta);
    conv2a_kernel<<<nblk, 256>>>(W2);
    conv2b_kernel<<<nblk, 256>>>(nbr, out);
}